// round 2
// baseline (speedup 1.0000x reference)
#include <cuda_runtime.h>

// Problem constants
#define NB    16      // window-batches
#define NTOK  16      // tokens per window
#define NBS   256     // NB*NTOK
#define NEMB  128     // channels
#define NC3   384     // 3*NEMB
#define NP    1024    // 32*32 grid points
#define NMODE 256     // 16*16 retained Fourier modes

// ---------------- device scratch (static; allocation-free) ----------------
__device__ float2 g_tw[32];                    // e^{+2pi i t/32}
__device__ float2 g_ytab[512];                 // inverse-DFT y-stage table [ky][v]
__device__ float  g_cpb[8 * 256];              // log-CPB bias [head][i][j]
__device__ float  g_attn[16 * 8 * 256];        // softmaxed attention
__device__ float2 g_Xf [NBS * NEMB * NMODE];   // forward DFT, (bs,c)-major
__device__ float2 g_XfT[NMODE * NBS * NEMB];   // mode-major for GEMM A
__device__ float2 g_Yf [NMODE * NBS * NC3];    // GEMM output, mode-major
__device__ float2 g_YfT[NBS * NC3 * NMODE];    // (bs,o)-major for inverse DFT
__device__ float2 g_WqT[NMODE * NEMB * NC3];   // qkv weights, mode-major
__device__ float2 g_WoT[NMODE * NEMB * NEMB];  // out weights, mode-major
__device__ float  g_qkv[NBS * NC3 * NP];       // spatial q|k|v
__device__ float  g_sa [NBS * NEMB * NP];      // attention output

// ---------------- init: twiddle tables ----------------
__global__ void k_init() {
    int t = threadIdx.x;  // 512 threads
    if (t < 32) {
        float s, c;
        sincospif((float)t * (1.0f / 16.0f), &s, &c);
        g_tw[t] = make_float2(c, s);
    }
    int ky = t >> 5, v = t & 31;
    float2 w;
    if (ky == 0) {
        w = make_float2(0.5f, 0.0f);   // folds the "Re(G0) once, others twice" rule
    } else {
        float s, c;
        sincospif((float)(ky * v) * (1.0f / 16.0f), &s, &c);
        w = make_float2(c, s);
    }
    g_ytab[t] = w;
}

// ---------------- log-spaced continuous position bias ----------------
__global__ void k_cpb(const float* __restrict__ w1, const float* __restrict__ b1,
                      const float* __restrict__ w2) {
    int t = threadIdx.x;               // 256 threads; one (i,j) pair each
    int i = t >> 4, j = t & 15;
    float rx = (float)((i >> 2) - (j >> 2));
    float ry = (float)((i & 3) - (j & 3));
    float ax = log2f(1.0f + fabsf(rx)) * (8.0f / 3.0f);
    float ay = log2f(1.0f + fabsf(ry)) * (8.0f / 3.0f);
    ax = copysignf(ax, rx);
    ay = copysignf(ay, ry);
    float acc[8];
#pragma unroll
    for (int q = 0; q < 8; q++) acc[q] = 0.0f;
    for (int h = 0; h < 512; h++) {
        float hv = fmaxf(ax * w1[h] + ay * w1[512 + h] + b1[h], 0.0f);
#pragma unroll
        for (int q = 0; q < 8; q++) acc[q] += hv * w2[h * 8 + q];
    }
#pragma unroll
    for (int q = 0; q < 8; q++) g_cpb[(q * 16 + i) * 16 + j] = acc[q];
}

// ---------------- weight transpose: [i,o,mode] (r,i planes) -> [mode][i*No+o] float2 ----------------
__global__ void k_wtrans(const float* __restrict__ wr, const float* __restrict__ wi, int which) {
    __shared__ float2 tile[32][33];
    int rows = which ? (NEMB * NEMB) : (NEMB * NC3);
    float2* out = which ? g_WoT : g_WqT;
    int c0 = blockIdx.x << 5, r0 = blockIdx.y << 5;
    int tx = threadIdx.x, ty = threadIdx.y;
#pragma unroll
    for (int q = 0; q < 4; q++) {
        int r = r0 + ty + (q << 3);
        tile[ty + (q << 3)][tx] = make_float2(wr[(long)r * 256 + c0 + tx],
                                              wi[(long)r * 256 + c0 + tx]);
    }
    __syncthreads();
#pragma unroll
    for (int q = 0; q < 4; q++)
        out[(long)(c0 + ty + (q << 3)) * rows + r0 + tx] = tile[tx][ty + (q << 3)];
}

// ---------------- generic float2 transpose between scratch buffers ----------------
__global__ void k_trans(int which, int rows, int cols) {
    const float2* __restrict__ in = which ? g_Yf : g_Xf;
    float2* __restrict__ out      = which ? g_YfT : g_XfT;
    __shared__ float2 tile[32][33];
    int c0 = blockIdx.x << 5, r0 = blockIdx.y << 5;
    int tx = threadIdx.x, ty = threadIdx.y;
#pragma unroll
    for (int q = 0; q < 4; q++)
        tile[ty + (q << 3)][tx] = in[(long)(r0 + ty + (q << 3)) * cols + c0 + tx];
    __syncthreads();
#pragma unroll
    for (int q = 0; q < 4; q++)
        out[(long)(c0 + ty + (q << 3)) * rows + r0 + tx] = tile[tx][ty + (q << 3)];
}

// ---------------- forward low-mode DFT (optionally with shifted-window gather) ----------------
__global__ void k_fwd(const float* __restrict__ seq, int shifted) {
    int bs = blockIdx.x, c = blockIdx.y;
    __shared__ float xs[1024];
    __shared__ float2 T[16][33];
    __shared__ float2 tw[32];
    int t = threadIdx.x;  // 256
    if (t < 32) tw[t] = g_tw[t];

    if (shifted) {
        int b = bs >> 4, s = bs & 15, qx = s >> 2, qy = s & 3;
#pragma unroll
        for (int q = 0; q < 4; q++) {
            int idx = t + (q << 8);
            int i = idx >> 5, j = idx & 31;
            int I = ((qx << 5) + i + 16) & 127;
            int J = ((qy << 5) + j + 16) & 127;
            int s2 = ((I >> 5) << 2) | (J >> 5);
            xs[idx] = seq[(((b * 16 + s2) * 128 + c) * NP) + ((I & 31) << 5) + (J & 31)];
        }
    } else {
        const float* p = g_sa + (long)(bs * NEMB + c) * NP;
#pragma unroll
        for (int q = 0; q < 4; q++) xs[t + (q << 8)] = p[t + (q << 8)];
    }
    __syncthreads();

    // stage 1: T[kx][v] = sum_u x[u][v] * e^{-2pi i kx u / 32}
#pragma unroll
    for (int q = 0; q < 2; q++) {
        int idx = t + (q << 8);
        int kx = idx >> 5, v = idx & 31;
        float tr = 0.0f, ti = 0.0f;
        int a = 0;
#pragma unroll
        for (int u = 0; u < 32; u++) {
            float x = xs[(u << 5) + v];
            float2 w = tw[a];
            tr += x * w.x;
            ti -= x * w.y;
            a = (a + kx) & 31;
        }
        T[kx][v] = make_float2(tr, ti);
    }
    __syncthreads();

    // stage 2: Xf[kx][ky] = sum_v T[kx][v] * e^{-2pi i ky v / 32}
    {
        int kx = t >> 4, ky = t & 15;
        float xr = 0.0f, xi = 0.0f;
        int a = 0;
#pragma unroll
        for (int v = 0; v < 32; v++) {
            float2 tv = T[kx][v];
            float2 w = tw[a];
            xr += tv.x * w.x + tv.y * w.y;
            xi += tv.y * w.x - tv.x * w.y;
            a = (a + ky) & 31;
        }
        g_Xf[(long)(bs * NEMB + c) * 256 + t] = make_float2(xr, xi);
    }
}

// ---------------- batched complex GEMM (per mode): C[bs,o] = sum_c A[bs,c] * W[c,o] ----------------
template <int N>
__global__ void k_gemm() {
    const float2* __restrict__ A = g_XfT;
    const float2* __restrict__ W = (N == 384) ? g_WqT : g_WoT;
    float2* __restrict__ C = g_Yf;

    __shared__ float2 As[16][65];  // padded to kill STS conflicts
    __shared__ float2 Ws[16][64];

    int mo = blockIdx.z;
    const float2* Ab = A + (long)mo * (256 * 128) + (long)blockIdx.y * 64 * 128;
    const float2* Wb = W + (long)mo * (128 * N) + blockIdx.x * 64;
    float2* Cb       = C + (long)mo * (256 * N) + (long)blockIdx.y * 64 * N + blockIdx.x * 64;

    int t = threadIdx.x;
    int tx = t & 15, ty = t >> 4;
    float2 acc[4][4];
#pragma unroll
    for (int i = 0; i < 4; i++)
#pragma unroll
        for (int j = 0; j < 4; j++) acc[i][j] = make_float2(0.0f, 0.0f);

    for (int k0 = 0; k0 < 128; k0 += 16) {
#pragma unroll
        for (int q = 0; q < 4; q++) {
            int lin = t + (q << 8);
            int mr = lin >> 4, kk = lin & 15;
            As[kk][mr] = Ab[mr * 128 + k0 + kk];
        }
#pragma unroll
        for (int q = 0; q < 4; q++) {
            int lin = t + (q << 8);
            int kk = lin >> 6, nn = lin & 63;
            Ws[kk][nn] = Wb[(k0 + kk) * N + nn];
        }
        __syncthreads();
#pragma unroll
        for (int kk = 0; kk < 16; kk++) {
            float2 a[4], bb[4];
#pragma unroll
            for (int i = 0; i < 4; i++) a[i] = As[kk][ty + i * 16];
#pragma unroll
            for (int j = 0; j < 4; j++) bb[j] = Ws[kk][tx + j * 16];
#pragma unroll
            for (int i = 0; i < 4; i++)
#pragma unroll
                for (int j = 0; j < 4; j++) {
                    acc[i][j].x += a[i].x * bb[j].x - a[i].y * bb[j].y;
                    acc[i][j].y += a[i].x * bb[j].y + a[i].y * bb[j].x;
                }
        }
        __syncthreads();
    }
#pragma unroll
    for (int i = 0; i < 4; i++)
#pragma unroll
        for (int j = 0; j < 4; j++)
            Cb[(ty + i * 16) * N + tx + j * 16] = acc[i][j];
}

// ---------------- inverse low-mode irfft2 (+residual or +unshifted store) ----------------
__global__ void k_inv(const float* __restrict__ seq, float* __restrict__ dout, int mode) {
    int bs = blockIdx.x, o = blockIdx.y;
    int nch = mode ? 128 : 384;
    __shared__ float2 Ssm[256];
    __shared__ float2 Gs[32][17];
    __shared__ float2 ytabs[512];
    __shared__ float2 tw[32];
    int t = threadIdx.x;  // 256
    if (t < 32) tw[t] = g_tw[t];
    ytabs[t]       = g_ytab[t];
    ytabs[t + 256] = g_ytab[t + 256];
    Ssm[t] = g_YfT[((long)bs * nch + o) * 256 + t];
    __syncthreads();

    // G[u][ky] = sum_kx S[kx][ky] * e^{+2pi i kx u / 32}
#pragma unroll
    for (int q = 0; q < 2; q++) {
        int idx = t + (q << 8);
        int u = idx >> 4, ky = idx & 15;
        float gr = 0.0f, gi = 0.0f;
        int a = 0;
#pragma unroll
        for (int kx = 0; kx < 16; kx++) {
            float2 s = Ssm[(kx << 4) + ky];
            float2 w = tw[a];
            gr += s.x * w.x - s.y * w.y;
            gi += s.x * w.y + s.y * w.x;
            a = (a + u) & 31;
        }
        Gs[u][ky] = make_float2(gr, gi);
    }
    __syncthreads();

    int b = bs >> 4, s = bs & 15, qx = s >> 2, qy = s & 3;
#pragma unroll
    for (int q = 0; q < 4; q++) {
        int idx = t + (q << 8);
        int u = idx >> 5, v = idx & 31;
        float acc = 0.0f;
#pragma unroll
        for (int ky = 0; ky < 16; ky++) {
            float2 g = Gs[u][ky];
            float2 w = ytabs[(ky << 5) + v];
            acc += g.x * w.x - g.y * w.y;   // Re(G * e^{+i th}); imag of DC column dropped (c2r rule)
        }
        float y = acc * (2.0f / 1024.0f);
        // image-coordinate +16 shift (forward residual gather / backward unshift scatter use same map)
        int I = ((qx << 5) + u + 16) & 127;
        int J = ((qy << 5) + v + 16) & 127;
        int s2 = ((I >> 5) << 2) | (J >> 5);
        long off = ((long)(b * 16 + s2) * 128) * NP + ((I & 31) << 5) + (J & 31);
        if (mode == 0) {
            y += seq[off + (long)(o & 127) * NP];   // residual concat([x,x,x])
            g_qkv[((long)bs * NC3 + o) * NP + idx] = y;
        } else {
            dout[off + (long)o * NP] = y;           // fused unshift write
        }
    }
}

// ---------------- attention scores + bias + softmax ----------------
__global__ void k_scores(const float* __restrict__ amask) {
    int b = blockIdx.x, n = blockIdx.y, i = blockIdx.z;
    int t = threadIdx.x;  // 256
    __shared__ float red[16][8];
    float acc[16];
#pragma unroll
    for (int j = 0; j < 16; j++) acc[j] = 0.0f;

    const float* qb = g_qkv + ((long)(b * 16 + i) * NC3 + n * 16) * NP;
    const float* kb = g_qkv + ((long)(b * 16) * NC3 + 128 + n * 16) * NP;

    for (int d = 0; d < 16; d++) {
        for (int p = t; p < 1024; p += 256) {
            float qv = qb[d * NP + p];
#pragma unroll
            for (int j = 0; j < 16; j++)
                acc[j] += qv * kb[(long)j * NC3 * NP + d * NP + p];
        }
    }
    int lane = t & 31, w = t >> 5;
#pragma unroll
    for (int j = 0; j < 16; j++) {
        float v = acc[j];
#pragma unroll
        for (int off = 16; off; off >>= 1) v += __shfl_xor_sync(0xffffffffu, v, off);
        if (lane == 0) red[j][w] = v;
    }
    __syncthreads();
    if (t < 16) {
        float s = 0.0f;
#pragma unroll
        for (int ww = 0; ww < 8; ww++) s += red[t][ww];
        s *= (1.0f / 4096.0f);  // 1/(h*w*sqrt(head_dim))
        int wdw = b & 3;
        s += amask[((wdw * 8 + n) * 16 + i) * 16 + t] + g_cpb[(n * 16 + i) * 16 + t];
        float m = s;
#pragma unroll
        for (int off = 8; off; off >>= 1) m = fmaxf(m, __shfl_xor_sync(0xffffu, m, off));
        float e = expf(s - m);
        float su = e;
#pragma unroll
        for (int off = 8; off; off >>= 1) su += __shfl_xor_sync(0xffffu, su, off);
        g_attn[((b * 8 + n) * 16 + i) * 16 + t] = e / su;
    }
}

// ---------------- attention x V ----------------
__global__ void k_sa() {
    int b = blockIdx.x, c = blockIdx.y;
    int n = c >> 4;
    __shared__ float a[256];
    int t = threadIdx.x;  // 256
    a[t] = g_attn[(b * 8 + n) * 256 + t];
    __syncthreads();
    const float* vb = g_qkv + ((long)(b * 16) * NC3 + 256 + c) * NP;
    float* ob = g_sa + ((long)(b * 16) * NEMB + c) * NP;
    for (int p0 = 0; p0 < 1024; p0 += 256) {
        int p = p0 + t;
        float vj[16];
#pragma unroll
        for (int j = 0; j < 16; j++) vj[j] = vb[(long)j * NC3 * NP + p];
#pragma unroll
        for (int i = 0; i < 16; i++) {
            float s = 0.0f;
#pragma unroll
            for (int j = 0; j < 16; j++) s += a[i * 16 + j] * vj[j];
            ob[(long)i * NEMB * NP + p] = s;
        }
    }
}

// ---------------- launch ----------------
extern "C" void kernel_launch(void* const* d_in, const int* in_sizes, int n_in,
                              void* d_out, int out_size) {
    const float* seq    = (const float*)d_in[0];
    const float* qkv_wr = (const float*)d_in[1];
    const float* qkv_wi = (const float*)d_in[2];
    const float* out_wr = (const float*)d_in[3];
    const float* out_wi = (const float*)d_in[4];
    const float* cpb_w1 = (const float*)d_in[5];
    const float* cpb_b1 = (const float*)d_in[6];
    const float* cpb_w2 = (const float*)d_in[7];
    const float* amask  = (const float*)d_in[8];
    float* outp = (float*)d_out;

    k_init<<<1, 512>>>();
    k_cpb<<<1, 256>>>(cpb_w1, cpb_b1, cpb_w2);
    k_wtrans<<<dim3(8, 1536), dim3(32, 8)>>>(qkv_wr, qkv_wi, 0);
    k_wtrans<<<dim3(8, 512),  dim3(32, 8)>>>(out_wr, out_wi, 1);

    // --- qkv spectral conv (with fused window shift on input) ---
    k_fwd<<<dim3(256, 128), 256>>>(seq, 1);
    k_trans<<<dim3(8, 1024), dim3(32, 8)>>>(0, 32768, 256);      // Xf -> XfT
    k_gemm<384><<<dim3(6, 4, 256), 256>>>();
    k_trans<<<dim3(3072, 8), dim3(32, 8)>>>(1, 256, 98304);      // Yf -> YfT
    k_inv<<<dim3(256, 384), 256>>>(seq, nullptr, 0);             // + residual -> g_qkv

    // --- attention ---
    k_scores<<<dim3(16, 8, 16), 256>>>(amask);
    k_sa<<<dim3(16, 128), 256>>>();

    // --- output spectral conv (with fused un-shift on output) ---
    k_fwd<<<dim3(256, 128), 256>>>(nullptr, 0);
    k_trans<<<dim3(8, 1024), dim3(32, 8)>>>(0, 32768, 256);
    k_gemm<128><<<dim3(2, 4, 256), 256>>>();
    k_trans<<<dim3(1024, 8), dim3(32, 8)>>>(1, 256, 32768);
    k_inv<<<dim3(256, 128), 256>>>(nullptr, outp, 1);
}

// round 3
// speedup vs baseline: 1.4570x; 1.4570x over previous
#include <cuda_runtime.h>

// Problem constants
#define NB    16      // window-batches
#define NTOK  16      // tokens per window
#define NBS   256     // NB*NTOK
#define NEMB  128     // channels
#define NC3   384     // 3*NEMB
#define NP    1024    // 32*32 grid points
#define NMODE 256     // 16*16 retained Fourier modes

#define S2f  1.41421356237f
#define IS2f 0.70710678119f

// ---------------- device scratch (static; allocation-free) ----------------
__device__ float2 g_tw[32];                    // e^{+2pi i t/32}
__device__ float2 g_ytab[512];                 // inverse-DFT y-stage table [ky][v]
__device__ float  g_cpb[8 * 256];              // log-CPB bias [head][i][j]
__device__ float  g_attn[16 * 8 * 256];        // softmaxed attention
__device__ float  g_gram[16 * 128 * 256];      // spatial token Gram [b][c][i*16+j]
__device__ float2 g_Xf [NBS * NEMB * NMODE];   // forward DFT, [bs][c][m]
__device__ float2 g_XfT[NMODE * NBS * NEMB];   // [m][bs][c] for GEMM A
__device__ float2 g_Yf [NMODE * NBS * NC3];    // GEMM output, [m][bs][o]
__device__ float2 g_YfT[NBS * NEMB * NMODE];   // [bs][o][m] for final inverse DFT
__device__ float2 g_WqT[NMODE * NEMB * NC3];   // qkv weights, mode-major
__device__ float2 g_WoT[NMODE * NEMB * NEMB];  // out weights, mode-major
__device__ float  g_Fq [NBS * 512 * NEMB];     // q-side Parseval features [bs][512][c]
__device__ float  g_Fk [NBS * 512 * NEMB];     // k-side features
__device__ float  g_gx [NBS * 512 * NEMB];     // x-only features (subtract term)
__device__ float2 g_Veff[NBS * NMODE * NEMB];  // effective v spectrum [bs][m][c]
__device__ float2 g_SaT[NMODE * NBS * NEMB];   // attn-mixed spectrum [m][bs][c]

// ---------------- init: twiddle tables ----------------
__global__ void k_init() {
    int t = threadIdx.x;  // 512 threads
    if (t < 32) {
        float s, c;
        sincospif((float)t * (1.0f / 16.0f), &s, &c);
        g_tw[t] = make_float2(c, s);
    }
    int ky = t >> 5, v = t & 31;
    float2 w;
    if (ky == 0) {
        w = make_float2(0.5f, 0.0f);   // folds the "Re(G0) once, others twice" rule
    } else {
        float s, c;
        sincospif((float)(ky * v) * (1.0f / 16.0f), &s, &c);
        w = make_float2(c, s);
    }
    g_ytab[t] = w;
}

// ---------------- log-spaced continuous position bias ----------------
__global__ void k_cpb(const float* __restrict__ w1, const float* __restrict__ b1,
                      const float* __restrict__ w2) {
    int t = threadIdx.x;               // 256 threads; one (i,j) pair each
    int i = t >> 4, j = t & 15;
    float rx = (float)((i >> 2) - (j >> 2));
    float ry = (float)((i & 3) - (j & 3));
    float ax = log2f(1.0f + fabsf(rx)) * (8.0f / 3.0f);
    float ay = log2f(1.0f + fabsf(ry)) * (8.0f / 3.0f);
    ax = copysignf(ax, rx);
    ay = copysignf(ay, ry);
    float acc[8];
#pragma unroll
    for (int q = 0; q < 8; q++) acc[q] = 0.0f;
    for (int h = 0; h < 512; h++) {
        float hv = fmaxf(ax * w1[h] + ay * w1[512 + h] + b1[h], 0.0f);
#pragma unroll
        for (int q = 0; q < 8; q++) acc[q] += hv * w2[h * 8 + q];
    }
#pragma unroll
    for (int q = 0; q < 8; q++) g_cpb[(q * 16 + i) * 16 + j] = acc[q];
}

// ---------------- weight transpose: [i,o,mode] (r,i planes) -> [mode][i*No+o] float2 ----------------
__global__ void k_wtrans(const float* __restrict__ wr, const float* __restrict__ wi, int which) {
    __shared__ float2 tile[32][33];
    int rows = which ? (NEMB * NEMB) : (NEMB * NC3);
    float2* out = which ? g_WoT : g_WqT;
    int c0 = blockIdx.x << 5, r0 = blockIdx.y << 5;
    int tx = threadIdx.x, ty = threadIdx.y;
#pragma unroll
    for (int q = 0; q < 4; q++) {
        int r = r0 + ty + (q << 3);
        tile[ty + (q << 3)][tx] = make_float2(wr[(long)r * 256 + c0 + tx],
                                              wi[(long)r * 256 + c0 + tx]);
    }
    __syncthreads();
#pragma unroll
    for (int q = 0; q < 4; q++)
        out[(long)(c0 + ty + (q << 3)) * rows + r0 + tx] = tile[tx][ty + (q << 3)];
}

// ---------------- generic float2 transpose between scratch buffers ----------------
__global__ void k_trans(int which, int rows, int cols) {
    const float2* __restrict__ in = which ? g_Yf : g_Xf;
    float2* __restrict__ out      = which ? g_YfT : g_XfT;
    __shared__ float2 tile[32][33];
    int c0 = blockIdx.x << 5, r0 = blockIdx.y << 5;
    int tx = threadIdx.x, ty = threadIdx.y;
#pragma unroll
    for (int q = 0; q < 4; q++)
        tile[ty + (q << 3)][tx] = in[(long)(r0 + ty + (q << 3)) * cols + c0 + tx];
    __syncthreads();
#pragma unroll
    for (int q = 0; q < 4; q++)
        out[(long)(c0 + ty + (q << 3)) * rows + r0 + tx] = tile[tx][ty + (q << 3)];
}

// ---------------- forward low-mode DFT with fused shifted-window gather ----------------
__global__ void k_fwd(const float* __restrict__ seq) {
    int bs = blockIdx.x, c = blockIdx.y;
    __shared__ float xs[1024];
    __shared__ float2 T[16][33];
    __shared__ float2 tw[32];
    int t = threadIdx.x;  // 256
    if (t < 32) tw[t] = g_tw[t];

    int b = bs >> 4, s = bs & 15, qx = s >> 2, qy = s & 3;
#pragma unroll
    for (int q = 0; q < 4; q++) {
        int idx = t + (q << 8);
        int i = idx >> 5, j = idx & 31;
        int I = ((qx << 5) + i + 16) & 127;
        int J = ((qy << 5) + j + 16) & 127;
        int s2 = ((I >> 5) << 2) | (J >> 5);
        xs[idx] = seq[(((b * 16 + s2) * 128 + c) * NP) + ((I & 31) << 5) + (J & 31)];
    }
    __syncthreads();

    // stage 1: T[kx][v] = sum_u x[u][v] * e^{-2pi i kx u / 32}
#pragma unroll
    for (int q = 0; q < 2; q++) {
        int idx = t + (q << 8);
        int kx = idx >> 5, v = idx & 31;
        float tr = 0.0f, ti = 0.0f;
        int a = 0;
#pragma unroll
        for (int u = 0; u < 32; u++) {
            float x = xs[(u << 5) + v];
            float2 w = tw[a];
            tr += x * w.x;
            ti -= x * w.y;
            a = (a + kx) & 31;
        }
        T[kx][v] = make_float2(tr, ti);
    }
    __syncthreads();

    // stage 2: Xf[kx][ky] = sum_v T[kx][v] * e^{-2pi i ky v / 32}
    {
        int kx = t >> 4, ky = t & 15;
        float xr = 0.0f, xi = 0.0f;
        int a = 0;
#pragma unroll
        for (int v = 0; v < 32; v++) {
            float2 tv = T[kx][v];
            float2 w = tw[a];
            xr += tv.x * w.x + tv.y * w.y;
            xi += tv.y * w.x - tv.x * w.y;
            a = (a + ky) & 31;
        }
        g_Xf[(long)(bs * NEMB + c) * 256 + t] = make_float2(xr, xi);
    }
}

// ---------------- spatial token Gram (shifted windows): g_gram[b][c][i][j] = sum_p x_i x_j ----------------
__global__ void k_gram(const float* __restrict__ seq) {
    int b = blockIdx.x, c = blockIdx.y;           // grid (16, 128)
    __shared__ float tiles[16][516];              // 16 tokens x 512 positions (padded)
    int t = threadIdx.x;                          // 256
    int ti = (t >> 2) & 3, tj = t & 3, g = t >> 4;
    float acc[4][4];
#pragma unroll
    for (int ii = 0; ii < 4; ii++)
#pragma unroll
        for (int jj = 0; jj < 4; jj++) acc[ii][jj] = 0.0f;

    for (int ph = 0; ph < 2; ph++) {
#pragma unroll
        for (int k = 0; k < 32; k++) {
            int e = t + (k << 8);                 // 8192 = 16 tok x 512 pos
            int s = e >> 9, pl = e & 511;
            int p = (ph << 9) + pl;
            int u = p >> 5, v = p & 31;
            int qx = s >> 2, qy = s & 3;
            int I = ((qx << 5) + u + 16) & 127;
            int J = ((qy << 5) + v + 16) & 127;
            int s2 = ((I >> 5) << 2) | (J >> 5);
            tiles[s][pl] = seq[(((b * 16 + s2) * 128 + c) * NP) + ((I & 31) << 5) + (J & 31)];
        }
        __syncthreads();
#pragma unroll
        for (int w = 0; w < 32; w++) {
            int pl = (g << 5) + w;
            float av[4], bv[4];
#pragma unroll
            for (int ii = 0; ii < 4; ii++) av[ii] = tiles[ti * 4 + ii][pl];
#pragma unroll
            for (int jj = 0; jj < 4; jj++) bv[jj] = tiles[tj * 4 + jj][pl];
#pragma unroll
            for (int ii = 0; ii < 4; ii++)
#pragma unroll
                for (int jj = 0; jj < 4; jj++) acc[ii][jj] += av[ii] * bv[jj];
        }
        __syncthreads();
    }
    float* partials = &tiles[0][0];               // reuse smem: 256 pairs x 16 groups
#pragma unroll
    for (int ii = 0; ii < 4; ii++)
#pragma unroll
        for (int jj = 0; jj < 4; jj++)
            partials[(((ti * 4 + ii) << 4) + tj * 4 + jj) * 16 + g] = acc[ii][jj];
    __syncthreads();
    float ssum = 0.0f;
#pragma unroll
    for (int g2 = 0; g2 < 16; g2++) ssum += partials[t * 16 + g2];
    g_gram[(((b << 7) + c) << 8) + t] = ssum;
}

// ---------------- batched complex GEMM (per mode): C[bs,o] = sum_c A[bs,c] * W[c,o] ----------------
template <int N>
__global__ void k_gemm() {
    const float2* __restrict__ A = (N == 384) ? g_XfT : g_SaT;
    const float2* __restrict__ W = (N == 384) ? g_WqT : g_WoT;
    float2* __restrict__ C = g_Yf;

    __shared__ float2 As[16][65];  // padded to kill STS conflicts
    __shared__ float2 Ws[16][64];

    int mo = blockIdx.z;
    const float2* Ab = A + (long)mo * (256 * 128) + (long)blockIdx.y * 64 * 128;
    const float2* Wb = W + (long)mo * (128 * N) + blockIdx.x * 64;
    float2* Cb       = C + (long)mo * (256 * N) + (long)blockIdx.y * 64 * N + blockIdx.x * 64;

    int t = threadIdx.x;
    int tx = t & 15, ty = t >> 4;
    float2 acc[4][4];
#pragma unroll
    for (int i = 0; i < 4; i++)
#pragma unroll
        for (int j = 0; j < 4; j++) acc[i][j] = make_float2(0.0f, 0.0f);

    for (int k0 = 0; k0 < 128; k0 += 16) {
#pragma unroll
        for (int q = 0; q < 4; q++) {
            int lin = t + (q << 8);
            int mr = lin >> 4, kk = lin & 15;
            As[kk][mr] = Ab[mr * 128 + k0 + kk];
        }
#pragma unroll
        for (int q = 0; q < 4; q++) {
            int lin = t + (q << 8);
            int kk = lin >> 6, nn = lin & 63;
            Ws[kk][nn] = Wb[(k0 + kk) * N + nn];
        }
        __syncthreads();
#pragma unroll
        for (int kk = 0; kk < 16; kk++) {
            float2 a[4], bb[4];
#pragma unroll
            for (int i = 0; i < 4; i++) a[i] = As[kk][ty + i * 16];
#pragma unroll
            for (int j = 0; j < 4; j++) bb[j] = Ws[kk][tx + j * 16];
#pragma unroll
            for (int i = 0; i < 4; i++)
#pragma unroll
                for (int j = 0; j < 4; j++) {
                    acc[i][j].x += a[i].x * bb[j].x - a[i].y * bb[j].y;
                    acc[i][j].y += a[i].x * bb[j].y + a[i].y * bb[j].x;
                }
        }
        __syncthreads();
    }
#pragma unroll
    for (int i = 0; i < 4; i++)
#pragma unroll
        for (int j = 0; j < 4; j++)
            Cb[(ty + i * 16) * N + tx + j * 16] = acc[i][j];
}

// ---------------- build Parseval feature vectors + effective V spectrum ----------------
__global__ void k_feat() {
    int m = blockIdx.x;                 // mode
    int bs0 = blockIdx.y << 4;          // 16 bs per block
    int c = threadIdx.x;                // 128
    int ky = m & 15;
#pragma unroll 4
    for (int q = 0; q < 16; q++) {
        int bs = bs0 + q;
        float2 X = g_XfT[(long)m * 32768 + bs * 128 + c];
        const float2* Yb = g_Yf + (long)m * 98304 + bs * 384;
        float2 Q = Yb[c], K = Yb[128 + c], V = Yb[256 + c];
        float2 fq, fk, gx, ve;
        if (m == 0) {
            fq = make_float2(X.x + Q.x, 0.0f);
            fk = make_float2(X.x + K.x, 0.0f);
            gx = make_float2(X.x, 0.0f);
            ve = make_float2(X.x + V.x, 0.0f);
        } else if (ky == 0) {
            fq = make_float2(S2f * X.x + IS2f * Q.x, S2f * X.y + IS2f * Q.y);
            fk = make_float2(S2f * X.x + IS2f * K.x, S2f * X.y + IS2f * K.y);
            gx = make_float2(S2f * X.x, S2f * X.y);
            ve = make_float2(X.x + 0.5f * V.x, X.y + 0.5f * V.y);
        } else {
            fq = make_float2(S2f * (X.x + Q.x), S2f * (X.y + Q.y));
            fk = make_float2(S2f * (X.x + K.x), S2f * (X.y + K.y));
            gx = make_float2(S2f * X.x, S2f * X.y);
            ve = make_float2(X.x + V.x, X.y + V.y);
        }
        long fb = (long)bs * 65536 + (long)(2 * m) * 128 + c;
        g_Fq[fb] = fq.x; g_Fq[fb + 128] = fq.y;
        g_Fk[fb] = fk.x; g_Fk[fb + 128] = fk.y;
        g_gx[fb] = gx.x; g_gx[fb + 128] = gx.y;
        g_Veff[((long)bs * 256 + m) * 128 + c] = ve;
    }
}

// ---------------- scores (freq-domain Parseval Gram) + bias + softmax ----------------
__global__ void k_scores(const float* __restrict__ amask) {
    int b = blockIdx.x, n = blockIdx.y;  // grid (16, 8)
    __shared__ float sq[16 * 132], sk[16 * 132], sx[16 * 132];
    int t = threadIdx.x;                 // 256; thread = pair (i = t>>4, j = t&15)
    int i = t >> 4, j = t & 15;
    float D = 0.0f;

    for (int ch = 0; ch < 64; ch++) {    // 64 chunks x 8 feature-rows x 16 d = 8192 reduction
#pragma unroll
        for (int k = 0; k < 8; k++) {
            int e = t + (k << 8);
            int d = e & 15, mcL = (e >> 4) & 7, ii = e >> 7;
            long ga = (long)((b << 4) + ii) * 65536 + (long)((ch << 3) + mcL) * 128 + (n << 4) + d;
            int sa = ii * 132 + (mcL << 4) + d;
            sq[sa] = g_Fq[ga];
            sk[sa] = g_Fk[ga];
            sx[sa] = g_gx[ga];
        }
        __syncthreads();
        const float4* aq = (const float4*)(sq + i * 132);
        const float4* ak = (const float4*)(sk + j * 132);
        const float4* xi = (const float4*)(sx + i * 132);
        const float4* xj = (const float4*)(sx + j * 132);
#pragma unroll
        for (int r = 0; r < 32; r++) {
            float4 a = aq[r], bb = ak[r], u = xi[r], v = xj[r];
            D += a.x * bb.x + a.y * bb.y + a.z * bb.z + a.w * bb.w;
            D -= u.x * v.x + u.y * v.y + u.z * v.z + u.w * v.w;
        }
        __syncthreads();
    }

    float gsum = 0.0f;
#pragma unroll
    for (int d = 0; d < 16; d++)
        gsum += g_gram[(((b << 7) + (n << 4) + d) << 8) + t];

    float s = (gsum + D * (1.0f / 1024.0f)) * (1.0f / 4096.0f);
    s += amask[(((b & 3) * 8 + n) << 8) + t] + g_cpb[(n << 8) + t];
    float mx = s;
#pragma unroll
    for (int off = 8; off; off >>= 1) mx = fmaxf(mx, __shfl_xor_sync(0xffffffffu, mx, off));
    float e = expf(s - mx);
    float su = e;
#pragma unroll
    for (int off = 8; off; off >>= 1) su += __shfl_xor_sync(0xffffffffu, su, off);
    g_attn[((b * 8 + n) << 8) + t] = e / su;
}

// ---------------- attn x Veff in frequency domain -> g_SaT [m][bs][c] ----------------
__global__ void k_av() {
    int b = blockIdx.x, mch = blockIdx.y;   // grid (16, 128), 2 modes per block
    __shared__ float2 sV[16][2][128];
    __shared__ float sA[2048];
    int t = threadIdx.x;                    // 256
#pragma unroll
    for (int k = 0; k < 8; k++) sA[t + (k << 8)] = g_attn[b * 2048 + t + (k << 8)];
#pragma unroll
    for (int k = 0; k < 16; k++) {
        int e = t + (k << 8);               // 4096 float2
        int c = e & 127, mo = (e >> 7) & 1, j = e >> 8;
        sV[j][mo][c] = g_Veff[((long)((b << 4) + j) * 256 + (mch << 1) + mo) * 128 + c];
    }
    __syncthreads();
    int c = t & 127, mo = t >> 7;
    int n = c >> 4;
    float2 acc[16];
#pragma unroll
    for (int ii = 0; ii < 16; ii++) acc[ii] = make_float2(0.0f, 0.0f);
#pragma unroll
    for (int jj = 0; jj < 16; jj++) {
        float2 v = sV[jj][mo][c];
#pragma unroll
        for (int ii = 0; ii < 16; ii++) {
            float a = sA[(n << 8) + (ii << 4) + jj];
            acc[ii].x += a * v.x;
            acc[ii].y += a * v.y;
        }
    }
    int m = (mch << 1) + mo;
#pragma unroll
    for (int ii = 0; ii < 16; ii++)
        g_SaT[(long)m * 32768 + ((b << 4) + ii) * 128 + c] = acc[ii];
}

// ---------------- inverse low-mode irfft2 with fused un-shift store ----------------
__global__ void k_inv(float* __restrict__ dout) {
    int bs = blockIdx.x, o = blockIdx.y;
    __shared__ float2 Ssm[256];
    __shared__ float2 Gs[32][17];
    __shared__ float2 ytabs[512];
    __shared__ float2 tw[32];
    int t = threadIdx.x;  // 256
    if (t < 32) tw[t] = g_tw[t];
    ytabs[t]       = g_ytab[t];
    ytabs[t + 256] = g_ytab[t + 256];
    Ssm[t] = g_YfT[((long)bs * 128 + o) * 256 + t];
    __syncthreads();

    // G[u][ky] = sum_kx S[kx][ky] * e^{+2pi i kx u / 32}
#pragma unroll
    for (int q = 0; q < 2; q++) {
        int idx = t + (q << 8);
        int u = idx >> 4, ky = idx & 15;
        float gr = 0.0f, gi = 0.0f;
        int a = 0;
#pragma unroll
        for (int kx = 0; kx < 16; kx++) {
            float2 s = Ssm[(kx << 4) + ky];
            float2 w = tw[a];
            gr += s.x * w.x - s.y * w.y;
            gi += s.x * w.y + s.y * w.x;
            a = (a + u) & 31;
        }
        Gs[u][ky] = make_float2(gr, gi);
    }
    __syncthreads();

    int b = bs >> 4, s = bs & 15, qx = s >> 2, qy = s & 3;
#pragma unroll
    for (int q = 0; q < 4; q++) {
        int idx = t + (q << 8);
        int u = idx >> 5, v = idx & 31;
        float acc = 0.0f;
#pragma unroll
        for (int ky = 0; ky < 16; ky++) {
            float2 g = Gs[u][ky];
            float2 w = ytabs[(ky << 5) + v];
            acc += g.x * w.x - g.y * w.y;   // c2r projection semantics
        }
        float y = acc * (2.0f / 1024.0f);
        int I = ((qx << 5) + u + 16) & 127;
        int J = ((qy << 5) + v + 16) & 127;
        int s2 = ((I >> 5) << 2) | (J >> 5);
        long off = ((long)(b * 16 + s2) * 128) * NP + ((I & 31) << 5) + (J & 31);
        dout[off + (long)o * NP] = y;       // fused un-shift write
    }
}

// ---------------- launch ----------------
extern "C" void kernel_launch(void* const* d_in, const int* in_sizes, int n_in,
                              void* d_out, int out_size) {
    const float* seq    = (const float*)d_in[0];
    const float* qkv_wr = (const float*)d_in[1];
    const float* qkv_wi = (const float*)d_in[2];
    const float* out_wr = (const float*)d_in[3];
    const float* out_wi = (const float*)d_in[4];
    const float* cpb_w1 = (const float*)d_in[5];
    const float* cpb_b1 = (const float*)d_in[6];
    const float* cpb_w2 = (const float*)d_in[7];
    const float* amask  = (const float*)d_in[8];
    float* outp = (float*)d_out;

    k_init<<<1, 512>>>();
    k_cpb<<<1, 256>>>(cpb_w1, cpb_b1, cpb_w2);
    k_wtrans<<<dim3(8, 1536), dim3(32, 8)>>>(qkv_wr, qkv_wi, 0);
    k_wtrans<<<dim3(8, 512),  dim3(32, 8)>>>(out_wr, out_wi, 1);

    // forward DFT (fused window shift) + spatial token Gram
    k_fwd<<<dim3(256, 128), 256>>>(seq);
    k_gram<<<dim3(16, 128), 256>>>(seq);
    k_trans<<<dim3(8, 1024), dim3(32, 8)>>>(0, 32768, 256);      // Xf -> XfT [m][bs][c]

    // qkv spectral mixing (frequency domain only)
    k_gemm<384><<<dim3(6, 4, 256), 256>>>();

    // Parseval features + effective V spectrum
    k_feat<<<dim3(256, 16), 128>>>();

    // attention entirely in frequency domain
    k_scores<<<dim3(16, 8), 256>>>(amask);
    k_av<<<dim3(16, 128), 256>>>();

    // output spectral conv + fused un-shift
    k_gemm<128><<<dim3(2, 4, 256), 256>>>();
    k_trans<<<dim3(1024, 8), dim3(32, 8)>>>(1, 256, 32768);      // Yf -> YfT [bs][o][m]
    k_inv<<<dim3(256, 128), 256>>>(outp);
}

// round 4
// speedup vs baseline: 1.7381x; 1.1930x over previous
#include <cuda_runtime.h>
#include <cuda_bf16.h>

// Problem constants
#define NBS   256     // window-batches * tokens
#define NEMB  128
#define NP    1024
#define NMODE 256

#define S2f  1.41421356237f
#define IS2f 0.70710678119f

// ---------------- device scratch ----------------
__device__ float2 g_tw[32];
__device__ float2 g_ytab[512];
__device__ float  g_cpb[8 * 256];
__device__ float  g_attn[16 * 8 * 256];
__device__ float  g_gram[16 * 128 * 256];
__device__ float2 g_Xf [NBS * NEMB * NMODE];             // fwd DFT [bs*c][m]
__device__ __nv_bfloat16 g_Ab [256L * 256 * 2 * 256];    // A split  [m][bs][h][k]
__device__ __nv_bfloat16 g_Wbq[256L * 768 * 2 * 256];    // qkv W    [m][n][h][k]
__device__ __nv_bfloat16 g_Wbo[256L * 256 * 2 * 256];    // out W    [m][n][h][k]
__device__ float  g_C2q[256L * 256 * 768];               // qkv GEMM out [m][bs][n]
__device__ float  g_C2o[256L * 256 * 256];               // out GEMM out [m][bs][n]
__device__ float  g_Y2T[65536L * 256];                   // transposed for k_inv [j][m]
__device__ float  g_Fq [NBS * 512 * NEMB];
__device__ float  g_Fk [NBS * 512 * NEMB];
__device__ float  g_gx [NBS * 512 * NEMB];
__device__ float2 g_Veff[NBS * NMODE * NEMB];

__device__ __forceinline__ void bf_split(float v, __nv_bfloat16& h, __nv_bfloat16& l) {
    h = __float2bfloat16_rn(v);
    l = __float2bfloat16_rn(v - __bfloat162float(h));
}

// ---------------- init twiddles ----------------
__global__ void k_init() {
    int t = threadIdx.x;  // 512
    if (t < 32) {
        float s, c;
        sincospif((float)t * (1.0f / 16.0f), &s, &c);
        g_tw[t] = make_float2(c, s);
    }
    int ky = t >> 5, v = t & 31;
    float2 w;
    if (ky == 0) w = make_float2(0.5f, 0.0f);
    else { float s, c; sincospif((float)(ky * v) * (1.0f / 16.0f), &s, &c); w = make_float2(c, s); }
    g_ytab[t] = w;
}

// ---------------- log-CPB ----------------
__global__ void k_cpb(const float* __restrict__ w1, const float* __restrict__ b1,
                      const float* __restrict__ w2) {
    int t = threadIdx.x;
    int i = t >> 4, j = t & 15;
    float rx = (float)((i >> 2) - (j >> 2));
    float ry = (float)((i & 3) - (j & 3));
    float ax = log2f(1.0f + fabsf(rx)) * (8.0f / 3.0f);
    float ay = log2f(1.0f + fabsf(ry)) * (8.0f / 3.0f);
    ax = copysignf(ax, rx); ay = copysignf(ay, ry);
    float acc[8];
#pragma unroll
    for (int q = 0; q < 8; q++) acc[q] = 0.0f;
    for (int h = 0; h < 512; h++) {
        float hv = fmaxf(ax * w1[h] + ay * w1[512 + h] + b1[h], 0.0f);
#pragma unroll
        for (int q = 0; q < 8; q++) acc[q] += hv * w2[h * 8 + q];
    }
#pragma unroll
    for (int q = 0; q < 8; q++) g_cpb[(q * 16 + i) * 16 + j] = acc[q];
}

// ---------------- W prep: realify + bf16-split + [m][n][h][k] layout ----------------
__global__ void k_wprep(const float* __restrict__ wr, const float* __restrict__ wi, int which) {
    int No = which ? 128 : 384;
    __nv_bfloat16* dst = which ? g_Wbo : g_Wbq;
    int o = blockIdx.x, m0 = blockIdx.y << 5;
    __shared__ float sr[128][33], si[128][33];
    int t = threadIdx.x;  // 256
    int mi = t & 31, c0 = t >> 5;
#pragma unroll
    for (int it = 0; it < 16; it++) {
        int c = (it << 3) + c0;
        long src = ((long)c * No + o) * 256 + m0 + mi;
        sr[c][mi] = wr[src];
        si[c][mi] = wi[src];
    }
    __syncthreads();
    int w = t >> 5, lane = t & 31;
#pragma unroll
    for (int ml = 0; ml < 4; ml++) {
        int mi2 = (w << 2) + ml;
        long m = m0 + mi2;
        long bo  = (m * (long)(2 * No) + o) * 2 * 256;
        long boN = (m * (long)(2 * No) + No + o) * 2 * 256;
#pragma unroll
        for (int kl = 0; kl < 4; kl++) {
            int c = (kl << 5) + lane;
            float vr = sr[c][mi2], vi = si[c][mi2];
            __nv_bfloat16 h, l;
            bf_split(vr, h, l);  dst[bo + c] = h;        dst[bo + 256 + c] = l;
            bf_split(-vi, h, l); dst[bo + 128 + c] = h;  dst[bo + 384 + c] = l;
            bf_split(vi, h, l);  dst[boN + c] = h;       dst[boN + 256 + c] = l;
            bf_split(vr, h, l);  dst[boN + 128 + c] = h; dst[boN + 384 + c] = l;
        }
    }
}

// ---------------- forward low-mode DFT with fused shifted-window gather ----------------
__global__ void k_fwd(const float* __restrict__ seq) {
    int bs = blockIdx.x, c = blockIdx.y;
    __shared__ float xs[1024];
    __shared__ float2 T[16][33];
    __shared__ float2 tw[32];
    int t = threadIdx.x;  // 256
    if (t < 32) tw[t] = g_tw[t];

    int b = bs >> 4, s = bs & 15, qx = s >> 2, qy = s & 3;
#pragma unroll
    for (int q = 0; q < 4; q++) {
        int idx = t + (q << 8);
        int i = idx >> 5, j = idx & 31;
        int I = ((qx << 5) + i + 16) & 127;
        int J = ((qy << 5) + j + 16) & 127;
        int s2 = ((I >> 5) << 2) | (J >> 5);
        xs[idx] = seq[(((b * 16 + s2) * 128 + c) * NP) + ((I & 31) << 5) + (J & 31)];
    }
    __syncthreads();
#pragma unroll
    for (int q = 0; q < 2; q++) {
        int idx = t + (q << 8);
        int kx = idx >> 5, v = idx & 31;
        float tr = 0.0f, ti = 0.0f;
        int a = 0;
#pragma unroll
        for (int u = 0; u < 32; u++) {
            float x = xs[(u << 5) + v];
            float2 w = tw[a];
            tr += x * w.x; ti -= x * w.y;
            a = (a + kx) & 31;
        }
        T[kx][v] = make_float2(tr, ti);
    }
    __syncthreads();
    {
        int kx = t >> 4, ky = t & 15;
        float xr = 0.0f, xi = 0.0f;
        int a = 0;
#pragma unroll
        for (int v = 0; v < 32; v++) {
            float2 tv = T[kx][v];
            float2 w = tw[a];
            xr += tv.x * w.x + tv.y * w.y;
            xi += tv.y * w.x - tv.x * w.y;
            a = (a + ky) & 31;
        }
        g_Xf[(long)(bs * NEMB + c) * 256 + t] = make_float2(xr, xi);
    }
}

// ---------------- spatial token Gram ----------------
__global__ void k_gram(const float* __restrict__ seq) {
    int b = blockIdx.x, c = blockIdx.y;
    __shared__ float tiles[16][516];
    int t = threadIdx.x;
    int ti = (t >> 2) & 3, tj = t & 3, g = t >> 4;
    float acc[4][4];
#pragma unroll
    for (int ii = 0; ii < 4; ii++)
#pragma unroll
        for (int jj = 0; jj < 4; jj++) acc[ii][jj] = 0.0f;

    for (int ph = 0; ph < 2; ph++) {
#pragma unroll
        for (int k = 0; k < 32; k++) {
            int e = t + (k << 8);
            int s = e >> 9, pl = e & 511;
            int p = (ph << 9) + pl;
            int u = p >> 5, v = p & 31;
            int qx = s >> 2, qy = s & 3;
            int I = ((qx << 5) + u + 16) & 127;
            int J = ((qy << 5) + v + 16) & 127;
            int s2 = ((I >> 5) << 2) | (J >> 5);
            tiles[s][pl] = seq[(((b * 16 + s2) * 128 + c) * NP) + ((I & 31) << 5) + (J & 31)];
        }
        __syncthreads();
#pragma unroll
        for (int w = 0; w < 32; w++) {
            int pl = (g << 5) + w;
            float av[4], bv[4];
#pragma unroll
            for (int ii = 0; ii < 4; ii++) av[ii] = tiles[ti * 4 + ii][pl];
#pragma unroll
            for (int jj = 0; jj < 4; jj++) bv[jj] = tiles[tj * 4 + jj][pl];
#pragma unroll
            for (int ii = 0; ii < 4; ii++)
#pragma unroll
                for (int jj = 0; jj < 4; jj++) acc[ii][jj] += av[ii] * bv[jj];
        }
        __syncthreads();
    }
    float* partials = &tiles[0][0];
#pragma unroll
    for (int ii = 0; ii < 4; ii++)
#pragma unroll
        for (int jj = 0; jj < 4; jj++)
            partials[(((ti * 4 + ii) << 4) + tj * 4 + jj) * 16 + g] = acc[ii][jj];
    __syncthreads();
    float ssum = 0.0f;
#pragma unroll
    for (int g2 = 0; g2 < 16; g2++) ssum += partials[t * 16 + g2];
    g_gram[(((b << 7) + c) << 8) + t] = ssum;
}

// ---------------- A prep: transpose Xf -> realified split Ab ----------------
__global__ void k_prepA() {
    __shared__ float2 tile[32][33];
    int c0 = blockIdx.x << 5, r0 = blockIdx.y << 5;   // c0: m-tile, r0: (bs*c)-tile
    int tx = threadIdx.x, ty = threadIdx.y;
#pragma unroll
    for (int q = 0; q < 4; q++)
        tile[ty + (q << 3)][tx] = g_Xf[(long)(r0 + ty + (q << 3)) * 256 + c0 + tx];
    __syncthreads();
#pragma unroll
    for (int q = 0; q < 4; q++) {
        int m = c0 + ty + (q << 3);
        int row = r0 + tx;
        int bs = row >> 7, c = row & 127;
        float2 v = tile[tx][ty + (q << 3)];
        long base = ((long)m * 256 + bs) * 2 * 256;
        __nv_bfloat16 h, l;
        bf_split(v.x, h, l); g_Ab[base + c] = h;        g_Ab[base + 256 + c] = l;
        bf_split(v.y, h, l); g_Ab[base + 128 + c] = h;  g_Ab[base + 384 + c] = l;
    }
}

// ---------------- tensor-core GEMM: [256 x NT] = [256 x 256] * [256 x NT] per mode ----------------
template <int NT>
__global__ void __launch_bounds__(256, 1) k_gemm() {
    const __nv_bfloat16* __restrict__ Wb = (NT == 768) ? g_Wbq : g_Wbo;
    float* __restrict__ C = (NT == 768) ? g_C2q : g_C2o;
    __shared__ __nv_bfloat16 As[2][128][40];
    __shared__ __nv_bfloat16 Bs[2][128][40];

    int nb = blockIdx.x, mb = blockIdx.y, mo = blockIdx.z;
    int t = threadIdx.x;
    int wid = t >> 5, lane = t & 31;
    int wm = wid & 1, wn = wid >> 1;
    int g = lane >> 2, tq = lane & 3;

    float acc[4][4][4];
#pragma unroll
    for (int i = 0; i < 4; i++)
#pragma unroll
        for (int j = 0; j < 4; j++)
#pragma unroll
            for (int r = 0; r < 4; r++) acc[i][j][r] = 0.0f;

    const __nv_bfloat16* Abase = g_Ab + ((long)mo * 256 + mb * 128) * 2 * 256;
    const __nv_bfloat16* Bbase = Wb + ((long)mo * NT + nb * 128) * 2 * 256;

    int lr = t & 127, lh = t >> 7;
    for (int k0 = 0; k0 < 256; k0 += 32) {
        {
            const float4* sa = (const float4*)(Abase + ((long)lr * 2 + lh) * 256 + k0);
            float4* da = (float4*)&As[lh][lr][0];
            da[0] = sa[0]; da[1] = sa[1]; da[2] = sa[2]; da[3] = sa[3];
            const float4* sb = (const float4*)(Bbase + ((long)lr * 2 + lh) * 256 + k0);
            float4* db = (float4*)&Bs[lh][lr][0];
            db[0] = sb[0]; db[1] = sb[1]; db[2] = sb[2]; db[3] = sb[3];
        }
        __syncthreads();
#pragma unroll
        for (int ks = 0; ks < 2; ks++) {
            unsigned ah[4][4], al[4][4], bh[4][2], bl[4][2];
            int kb = ks * 16 + 2 * tq;
#pragma unroll
            for (int mt = 0; mt < 4; mt++) {
                int row = wm * 64 + mt * 16 + g;
                ah[mt][0] = *(const unsigned*)&As[0][row][kb];
                ah[mt][1] = *(const unsigned*)&As[0][row + 8][kb];
                ah[mt][2] = *(const unsigned*)&As[0][row][kb + 8];
                ah[mt][3] = *(const unsigned*)&As[0][row + 8][kb + 8];
                al[mt][0] = *(const unsigned*)&As[1][row][kb];
                al[mt][1] = *(const unsigned*)&As[1][row + 8][kb];
                al[mt][2] = *(const unsigned*)&As[1][row][kb + 8];
                al[mt][3] = *(const unsigned*)&As[1][row + 8][kb + 8];
            }
#pragma unroll
            for (int nt = 0; nt < 4; nt++) {
                int col = wn * 32 + nt * 8 + g;
                bh[nt][0] = *(const unsigned*)&Bs[0][col][kb];
                bh[nt][1] = *(const unsigned*)&Bs[0][col][kb + 8];
                bl[nt][0] = *(const unsigned*)&Bs[1][col][kb];
                bl[nt][1] = *(const unsigned*)&Bs[1][col][kb + 8];
            }
#define MMA(d, a, b0, b1)                                                     \
    asm volatile("mma.sync.aligned.m16n8k16.row.col.f32.bf16.bf16.f32 "       \
                 "{%0,%1,%2,%3}, {%4,%5,%6,%7}, {%8,%9}, {%0,%1,%2,%3};"      \
                 : "+f"(d[0]), "+f"(d[1]), "+f"(d[2]), "+f"(d[3])             \
                 : "r"(a[0]), "r"(a[1]), "r"(a[2]), "r"(a[3]), "r"(b0), "r"(b1))
#pragma unroll
            for (int mt = 0; mt < 4; mt++)
#pragma unroll
                for (int nt = 0; nt < 4; nt++) {
                    MMA(acc[mt][nt], ah[mt], bh[nt][0], bh[nt][1]);
                    MMA(acc[mt][nt], ah[mt], bl[nt][0], bl[nt][1]);
                    MMA(acc[mt][nt], al[mt], bh[nt][0], bh[nt][1]);
                }
#undef MMA
        }
        __syncthreads();
    }
#pragma unroll
    for (int mt = 0; mt < 4; mt++)
#pragma unroll
        for (int nt = 0; nt < 4; nt++) {
            int row = mb * 128 + wm * 64 + mt * 16 + g;
            long base = ((long)mo * 256 + row) * NT + nb * 128 + wn * 32 + nt * 8 + 2 * tq;
            *(float2*)&C[base] = make_float2(acc[mt][nt][0], acc[mt][nt][1]);
            *(float2*)&C[base + 8L * NT] = make_float2(acc[mt][nt][2], acc[mt][nt][3]);
        }
}

// ---------------- Parseval features + effective V spectrum ----------------
__global__ void k_feat() {
    int m = blockIdx.x;
    int bs0 = blockIdx.y << 4;
    int c = threadIdx.x;  // 128
    int ky = m & 15;
#pragma unroll 4
    for (int q = 0; q < 16; q++) {
        int bs = bs0 + q;
        const __nv_bfloat16* ab = g_Ab + ((long)m * 256 + bs) * 2 * 256;
        float2 X = make_float2(__bfloat162float(ab[c]) + __bfloat162float(ab[256 + c]),
                               __bfloat162float(ab[128 + c]) + __bfloat162float(ab[384 + c]));
        const float* Cb = g_C2q + ((long)m * 256 + bs) * 768;
        float2 Q = make_float2(Cb[c], Cb[384 + c]);
        float2 K = make_float2(Cb[128 + c], Cb[512 + c]);
        float2 V = make_float2(Cb[256 + c], Cb[640 + c]);
        float2 fq, fk, gx, ve;
        if (m == 0) {
            fq = make_float2(X.x + Q.x, 0.0f);
            fk = make_float2(X.x + K.x, 0.0f);
            gx = make_float2(X.x, 0.0f);
            ve = make_float2(X.x + V.x, 0.0f);
        } else if (ky == 0) {
            fq = make_float2(S2f * X.x + IS2f * Q.x, S2f * X.y + IS2f * Q.y);
            fk = make_float2(S2f * X.x + IS2f * K.x, S2f * X.y + IS2f * K.y);
            gx = make_float2(S2f * X.x, S2f * X.y);
            ve = make_float2(X.x + 0.5f * V.x, X.y + 0.5f * V.y);
        } else {
            fq = make_float2(S2f * (X.x + Q.x), S2f * (X.y + Q.y));
            fk = make_float2(S2f * (X.x + K.x), S2f * (X.y + K.y));
            gx = make_float2(S2f * X.x, S2f * X.y);
            ve = make_float2(X.x + V.x, X.y + V.y);
        }
        long fb = (long)bs * 65536 + (long)(2 * m) * 128 + c;
        g_Fq[fb] = fq.x; g_Fq[fb + 128] = fq.y;
        g_Fk[fb] = fk.x; g_Fk[fb + 128] = fk.y;
        g_gx[fb] = gx.x; g_gx[fb + 128] = gx.y;
        g_Veff[((long)bs * 256 + m) * 128 + c] = ve;
    }
}

// ---------------- scores + bias + softmax ----------------
__global__ void k_scores(const float* __restrict__ amask) {
    int b = blockIdx.x, n = blockIdx.y;
    __shared__ float sq[16 * 132], sk[16 * 132], sx[16 * 132];
    int t = threadIdx.x;
    int i = t >> 4, j = t & 15;
    float D = 0.0f;

    for (int ch = 0; ch < 64; ch++) {
#pragma unroll
        for (int k = 0; k < 8; k++) {
            int e = t + (k << 8);
            int d = e & 15, mcL = (e >> 4) & 7, ii = e >> 7;
            long ga = (long)((b << 4) + ii) * 65536 + (long)((ch << 3) + mcL) * 128 + (n << 4) + d;
            int sa = ii * 132 + (mcL << 4) + d;
            sq[sa] = g_Fq[ga];
            sk[sa] = g_Fk[ga];
            sx[sa] = g_gx[ga];
        }
        __syncthreads();
        const float4* aq = (const float4*)(sq + i * 132);
        const float4* ak = (const float4*)(sk + j * 132);
        const float4* xi = (const float4*)(sx + i * 132);
        const float4* xj = (const float4*)(sx + j * 132);
#pragma unroll
        for (int r = 0; r < 32; r++) {
            float4 a = aq[r], bb = ak[r], u = xi[r], v = xj[r];
            D += a.x * bb.x + a.y * bb.y + a.z * bb.z + a.w * bb.w;
            D -= u.x * v.x + u.y * v.y + u.z * v.z + u.w * v.w;
        }
        __syncthreads();
    }

    float gsum = 0.0f;
#pragma unroll
    for (int d = 0; d < 16; d++)
        gsum += g_gram[(((b << 7) + (n << 4) + d) << 8) + t];

    float s = (gsum + D * (1.0f / 1024.0f)) * (1.0f / 4096.0f);
    s += amask[(((b & 3) * 8 + n) << 8) + t] + g_cpb[(n << 8) + t];
    float mx = s;
#pragma unroll
    for (int off = 8; off; off >>= 1) mx = fmaxf(mx, __shfl_xor_sync(0xffffffffu, mx, off));
    float e = expf(s - mx);
    float su = e;
#pragma unroll
    for (int off = 8; off; off >>= 1) su += __shfl_xor_sync(0xffffffffu, su, off);
    g_attn[((b * 8 + n) << 8) + t] = e / su;
}

// ---------------- attn x Veff -> realified split A for out GEMM ----------------
__global__ void k_av() {
    int b = blockIdx.x, mch = blockIdx.y;
    __shared__ float2 sV[16][2][128];
    __shared__ float sA[2048];
    int t = threadIdx.x;
#pragma unroll
    for (int k = 0; k < 8; k++) sA[t + (k << 8)] = g_attn[b * 2048 + t + (k << 8)];
#pragma unroll
    for (int k = 0; k < 16; k++) {
        int e = t + (k << 8);
        int c = e & 127, mo = (e >> 7) & 1, j = e >> 8;
        sV[j][mo][c] = g_Veff[((long)((b << 4) + j) * 256 + (mch << 1) + mo) * 128 + c];
    }
    __syncthreads();
    int c = t & 127, mo = t >> 7;
    int n = c >> 4;
    float2 acc[16];
#pragma unroll
    for (int ii = 0; ii < 16; ii++) acc[ii] = make_float2(0.0f, 0.0f);
#pragma unroll
    for (int jj = 0; jj < 16; jj++) {
        float2 v = sV[jj][mo][c];
#pragma unroll
        for (int ii = 0; ii < 16; ii++) {
            float a = sA[(n << 8) + (ii << 4) + jj];
            acc[ii].x += a * v.x;
            acc[ii].y += a * v.y;
        }
    }
    int m = (mch << 1) + mo;
#pragma unroll
    for (int ii = 0; ii < 16; ii++) {
        int bs = (b << 4) + ii;
        long base = ((long)m * 256 + bs) * 2 * 256;
        __nv_bfloat16 h, l;
        bf_split(acc[ii].x, h, l); g_Ab[base + c] = h;       g_Ab[base + 256 + c] = l;
        bf_split(acc[ii].y, h, l); g_Ab[base + 128 + c] = h; g_Ab[base + 384 + c] = l;
    }
}

// ---------------- transpose C2o [m][j] -> Y2T [j][m] ----------------
__global__ void k_prepS() {
    __shared__ float tile[32][33];
    int c0 = blockIdx.x << 5, r0 = blockIdx.y << 5;   // c0: j, r0: m
    int tx = threadIdx.x, ty = threadIdx.y;
#pragma unroll
    for (int q = 0; q < 4; q++)
        tile[ty + (q << 3)][tx] = g_C2o[(long)(r0 + ty + (q << 3)) * 65536 + c0 + tx];
    __syncthreads();
#pragma unroll
    for (int q = 0; q < 4; q++)
        g_Y2T[(long)(c0 + ty + (q << 3)) * 256 + r0 + tx] = tile[tx][ty + (q << 3)];
}

// ---------------- inverse low-mode irfft2 with fused un-shift store ----------------
__global__ void k_inv(float* __restrict__ dout) {
    int bs = blockIdx.x, o = blockIdx.y;
    __shared__ float2 Ssm[256];
    __shared__ float2 Gs[32][17];
    __shared__ float2 ytabs[512];
    __shared__ float2 tw[32];
    int t = threadIdx.x;
    if (t < 32) tw[t] = g_tw[t];
    ytabs[t]       = g_ytab[t];
    ytabs[t + 256] = g_ytab[t + 256];
    Ssm[t] = make_float2(g_Y2T[((long)bs * 256 + o) * 256 + t],
                         g_Y2T[((long)bs * 256 + 128 + o) * 256 + t]);
    __syncthreads();
#pragma unroll
    for (int q = 0; q < 2; q++) {
        int idx = t + (q << 8);
        int u = idx >> 4, ky = idx & 15;
        float gr = 0.0f, gi = 0.0f;
        int a = 0;
#pragma unroll
        for (int kx = 0; kx < 16; kx++) {
            float2 s = Ssm[(kx << 4) + ky];
            float2 w = tw[a];
            gr += s.x * w.x - s.y * w.y;
            gi += s.x * w.y + s.y * w.x;
            a = (a + u) & 31;
        }
        Gs[u][ky] = make_float2(gr, gi);
    }
    __syncthreads();

    int b = bs >> 4, s = bs & 15, qx = s >> 2, qy = s & 3;
#pragma unroll
    for (int q = 0; q < 4; q++) {
        int idx = t + (q << 8);
        int u = idx >> 5, v = idx & 31;
        float acc = 0.0f;
#pragma unroll
        for (int ky = 0; ky < 16; ky++) {
            float2 g = Gs[u][ky];
            float2 w = ytabs[(ky << 5) + v];
            acc += g.x * w.x - g.y * w.y;
        }
        float y = acc * (2.0f / 1024.0f);
        int I = ((qx << 5) + u + 16) & 127;
        int J = ((qy << 5) + v + 16) & 127;
        int s2 = ((I >> 5) << 2) | (J >> 5);
        long off = ((long)(b * 16 + s2) * 128) * NP + ((I & 31) << 5) + (J & 31);
        dout[off + (long)o * NP] = y;
    }
}

// ---------------- launch ----------------
extern "C" void kernel_launch(void* const* d_in, const int* in_sizes, int n_in,
                              void* d_out, int out_size) {
    const float* seq    = (const float*)d_in[0];
    const float* qkv_wr = (const float*)d_in[1];
    const float* qkv_wi = (const float*)d_in[2];
    const float* out_wr = (const float*)d_in[3];
    const float* out_wi = (const float*)d_in[4];
    const float* cpb_w1 = (const float*)d_in[5];
    const float* cpb_b1 = (const float*)d_in[6];
    const float* cpb_w2 = (const float*)d_in[7];
    const float* amask  = (const float*)d_in[8];
    float* outp = (float*)d_out;

    k_init<<<1, 512>>>();
    k_cpb<<<1, 256>>>(cpb_w1, cpb_b1, cpb_w2);
    k_wprep<<<dim3(384, 8), 256>>>(qkv_wr, qkv_wi, 0);
    k_wprep<<<dim3(128, 8), 256>>>(out_wr, out_wi, 1);

    k_fwd<<<dim3(256, 128), 256>>>(seq);
    k_gram<<<dim3(16, 128), 256>>>(seq);
    k_prepA<<<dim3(8, 1024), dim3(32, 8)>>>();

    k_gemm<768><<<dim3(6, 2, 256), 256>>>();
    k_feat<<<dim3(256, 16), 128>>>();

    k_scores<<<dim3(16, 8), 256>>>(amask);
    k_av<<<dim3(16, 128), 256>>>();

    k_gemm<256><<<dim3(2, 2, 256), 256>>>();
    k_prepS<<<dim3(2048, 8), dim3(32, 8)>>>();
    k_inv<<<dim3(256, 128), 256>>>(outp);
}

// round 5
// speedup vs baseline: 1.8620x; 1.0713x over previous
#include <cuda_runtime.h>
#include <cuda_bf16.h>

#define NBS   256
#define NEMB  128
#define NP    1024
#define NMODE 256

#define S2f  1.41421356237f
#define IS2f 0.70710678119f

// ---------------- device scratch ----------------
__device__ float2 g_tw[32];
__device__ float2 g_ytab[512];
__device__ float  g_cpb[8 * 256];
__device__ float  g_attn[16 * 8 * 256];
__device__ float  g_gram[16 * 128 * 256];                // combined spatial - freq gram
__device__ float2 g_Xf [NBS * NEMB * NMODE];             // fwd DFT [bs*c][m]
__device__ __nv_bfloat16 g_Ab [256L * 256 * 2 * 256];    // A split [m][bs][h][re|im k]
__device__ __nv_bfloat16 g_Wqc[256L * 3 * 2 * 128 * 2 * 128]; // compact qkv W [m][o3][p][n][h][k]
__device__ __nv_bfloat16 g_Woc[256L * 2 * 128 * 2 * 128];     // compact out W [m][p][n][h][k]
__device__ float  g_C2o[256L * 256 * 256];               // out GEMM out [m][bs][n]
__device__ float  g_Y2T[65536L * 256];                   // transposed for k_inv
__device__ float  g_Fq [NBS * 512 * NEMB];               // [bs][2m+isIm][c]
__device__ float  g_Fk [NBS * 512 * NEMB];
__device__ float  g_VeR[NBS * NMODE * NEMB];             // Veff real plane [bs][m][c]
__device__ float  g_VeI[NBS * NMODE * NEMB];

__device__ __forceinline__ void bf_split(float v, __nv_bfloat16& h, __nv_bfloat16& l) {
    h = __float2bfloat16_rn(v);
    l = __float2bfloat16_rn(v - __bfloat162float(h));
}

// ---------------- init twiddles ----------------
__global__ void k_init() {
    int t = threadIdx.x;  // 512
    if (t < 32) {
        float s, c;
        sincospif((float)t * (1.0f / 16.0f), &s, &c);
        g_tw[t] = make_float2(c, s);
    }
    int ky = t >> 5, v = t & 31;
    float2 w;
    if (ky == 0) w = make_float2(0.5f, 0.0f);
    else { float s, c; sincospif((float)(ky * v) * (1.0f / 16.0f), &s, &c); w = make_float2(c, s); }
    g_ytab[t] = w;
}

// ---------------- log-CPB ----------------
__global__ void k_cpb(const float* __restrict__ w1, const float* __restrict__ b1,
                      const float* __restrict__ w2) {
    int t = threadIdx.x;
    int i = t >> 4, j = t & 15;
    float rx = (float)((i >> 2) - (j >> 2));
    float ry = (float)((i & 3) - (j & 3));
    float ax = log2f(1.0f + fabsf(rx)) * (8.0f / 3.0f);
    float ay = log2f(1.0f + fabsf(ry)) * (8.0f / 3.0f);
    ax = copysignf(ax, rx); ay = copysignf(ay, ry);
    float acc[8];
#pragma unroll
    for (int q = 0; q < 8; q++) acc[q] = 0.0f;
    for (int h = 0; h < 512; h++) {
        float hv = fmaxf(ax * w1[h] + ay * w1[512 + h] + b1[h], 0.0f);
#pragma unroll
        for (int q = 0; q < 8; q++) acc[q] += hv * w2[h * 8 + q];
    }
#pragma unroll
    for (int q = 0; q < 8; q++) g_cpb[(q * 16 + i) * 16 + j] = acc[q];
}

// ---------------- W prep: fold residual+mode weights, compact split planes ----------------
__global__ void k_wprep(const float* __restrict__ wr, const float* __restrict__ wi, int which) {
    int No = which ? 128 : 384;
    int o = blockIdx.x, m0 = blockIdx.y << 5;
    __shared__ float sr[128][33], si[128][33];
    int t = threadIdx.x;  // 256
    int mi = t & 31, c0 = t >> 5;
#pragma unroll
    for (int it = 0; it < 16; it++) {
        int c = (it << 3) + c0;
        long src = ((long)c * No + o) * 256 + m0 + mi;
        sr[c][mi] = wr[src];
        si[c][mi] = wi[src];
    }
    __syncthreads();
    int w = t >> 5, lane = t & 31;
    int oI = o >> 7, n = o & 127;
#pragma unroll
    for (int ml = 0; ml < 4; ml++) {
        int mi2 = (w << 2) + ml;
        long m = m0 + mi2;
        int ky = (int)(m & 15);
        float a, bco; int zim;
        if (which) { a = 0.0f; bco = 1.0f; zim = 0; }          // out conv: plain W
        else if (oI == 2) {                                    // Veff = X(I + w Wv)
            a = 1.0f; bco = (m == 0) ? 1.0f : ((ky == 0) ? 0.5f : 1.0f); zim = (m == 0);
        } else {                                               // Fq/Fk = X(aI + b W)
            if (m == 0)       { a = 1.0f;  bco = 1.0f;  zim = 1; }
            else if (ky == 0) { a = S2f;   bco = IS2f;  zim = 0; }
            else              { a = S2f;   bco = S2f;   zim = 0; }
        }
        long base = which ? ((m * 2) * 128 + n) * 2 * 128
                          : (((m * 3 + oI) * 2) * 128 + n) * 2 * 128;
        long pstride = (long)128 * 2 * 128;  // plane stride (p dim)
        __nv_bfloat16* dst = which ? g_Woc : g_Wqc;
#pragma unroll
        for (int kl = 0; kl < 4; kl++) {
            int k = (kl << 5) + lane;
            float vr = bco * sr[k][mi2] + ((k == n) ? a : 0.0f);
            if (which && k == n) vr = sr[k][mi2];  // out conv: no diag (a=0 handled), keep plain
            float vi = zim ? 0.0f : bco * si[k][mi2];
            __nv_bfloat16 h, l;
            bf_split(vr, h, l);
            dst[base + k] = h;                    // p=0 (re), h=0
            dst[base + 128 + k] = l;              // p=0, h=1
            bf_split(vi, h, l);
            dst[base + pstride + k] = h;          // p=1 (im), h=0
            dst[base + pstride + 128 + k] = l;    // p=1, h=1
        }
    }
}

// ---------------- forward low-mode DFT with fused shifted-window gather ----------------
__global__ void k_fwd(const float* __restrict__ seq) {
    int bs = blockIdx.x, c = blockIdx.y;
    __shared__ float xs[1024];
    __shared__ float2 T[16][33];
    __shared__ float2 tw[32];
    int t = threadIdx.x;  // 256
    if (t < 32) tw[t] = g_tw[t];

    int b = bs >> 4, s = bs & 15, qx = s >> 2, qy = s & 3;
#pragma unroll
    for (int q = 0; q < 4; q++) {
        int idx = t + (q << 8);
        int i = idx >> 5, j = idx & 31;
        int I = ((qx << 5) + i + 16) & 127;
        int J = ((qy << 5) + j + 16) & 127;
        int s2 = ((I >> 5) << 2) | (J >> 5);
        xs[idx] = seq[(((b * 16 + s2) * 128 + c) * NP) + ((I & 31) << 5) + (J & 31)];
    }
    __syncthreads();
#pragma unroll
    for (int q = 0; q < 2; q++) {
        int idx = t + (q << 8);
        int kx = idx >> 5, v = idx & 31;
        float tr = 0.0f, ti = 0.0f;
        int a = 0;
#pragma unroll
        for (int u = 0; u < 32; u++) {
            float x = xs[(u << 5) + v];
            float2 w = tw[a];
            tr += x * w.x; ti -= x * w.y;
            a = (a + kx) & 31;
        }
        T[kx][v] = make_float2(tr, ti);
    }
    __syncthreads();
    {
        int kx = t >> 4, ky = t & 15;
        float xr = 0.0f, xi = 0.0f;
        int a = 0;
#pragma unroll
        for (int v = 0; v < 32; v++) {
            float2 tv = T[kx][v];
            float2 w = tw[a];
            xr += tv.x * w.x + tv.y * w.y;
            xi += tv.y * w.x - tv.x * w.y;
            a = (a + ky) & 31;
        }
        g_Xf[(long)(bs * NEMB + c) * 256 + t] = make_float2(xr, xi);
    }
}

// ---------------- spatial token Gram ----------------
__global__ void k_gram(const float* __restrict__ seq) {
    int b = blockIdx.x, c = blockIdx.y;
    __shared__ float tiles[16][516];
    int t = threadIdx.x;
    int ti = (t >> 2) & 3, tj = t & 3, g = t >> 4;
    float acc[4][4];
#pragma unroll
    for (int ii = 0; ii < 4; ii++)
#pragma unroll
        for (int jj = 0; jj < 4; jj++) acc[ii][jj] = 0.0f;

    for (int ph = 0; ph < 2; ph++) {
#pragma unroll
        for (int k = 0; k < 32; k++) {
            int e = t + (k << 8);
            int s = e >> 9, pl = e & 511;
            int p = (ph << 9) + pl;
            int u = p >> 5, v = p & 31;
            int qx = s >> 2, qy = s & 3;
            int I = ((qx << 5) + u + 16) & 127;
            int J = ((qy << 5) + v + 16) & 127;
            int s2 = ((I >> 5) << 2) | (J >> 5);
            tiles[s][pl] = seq[(((b * 16 + s2) * 128 + c) * NP) + ((I & 31) << 5) + (J & 31)];
        }
        __syncthreads();
#pragma unroll
        for (int w = 0; w < 32; w++) {
            int pl = (g << 5) + w;
            float av[4], bv[4];
#pragma unroll
            for (int ii = 0; ii < 4; ii++) av[ii] = tiles[ti * 4 + ii][pl];
#pragma unroll
            for (int jj = 0; jj < 4; jj++) bv[jj] = tiles[tj * 4 + jj][pl];
#pragma unroll
            for (int ii = 0; ii < 4; ii++)
#pragma unroll
                for (int jj = 0; jj < 4; jj++) acc[ii][jj] += av[ii] * bv[jj];
        }
        __syncthreads();
    }
    float* partials = &tiles[0][0];
#pragma unroll
    for (int ii = 0; ii < 4; ii++)
#pragma unroll
        for (int jj = 0; jj < 4; jj++)
            partials[(((ti * 4 + ii) << 4) + tj * 4 + jj) * 16 + g] = acc[ii][jj];
    __syncthreads();
    float ssum = 0.0f;
#pragma unroll
    for (int g2 = 0; g2 < 16; g2++) ssum += partials[t * 16 + g2];
    g_gram[(((b << 7) + c) << 8) + t] = ssum;
}

// ---------------- subtract frequency-domain x-gram into g_gram ----------------
__global__ void k_gram2() {
    int b = blockIdx.x, c = blockIdx.y;     // (16, 128)
    __shared__ float2 sX[16][257];
    int t = threadIdx.x;                    // 256
#pragma unroll
    for (int j = 0; j < 16; j++)
        sX[j][t] = g_Xf[((long)((b * 16 + j) * 128 + c)) * 256 + t];
    __syncthreads();
    int i = t >> 4, j = t & 15;
    float2 x0i = sX[i][0], x0j = sX[j][0];
    float acc = -(x0i.x * x0j.x);           // DC weight 1 vs loop's 2
#pragma unroll 8
    for (int m = 0; m < 256; m++) {
        float2 xi = sX[i][m], xj = sX[j][m];
        acc += 2.0f * (xi.x * xj.x + xi.y * xj.y);
    }
    g_gram[(((b << 7) + c) << 8) + t] -= acc * (1.0f / 1024.0f);
}

// ---------------- A prep: transpose Xf -> realified split Ab ----------------
__global__ void k_prepA() {
    __shared__ float2 tile[32][33];
    int c0 = blockIdx.x << 5, r0 = blockIdx.y << 5;
    int tx = threadIdx.x, ty = threadIdx.y;
#pragma unroll
    for (int q = 0; q < 4; q++)
        tile[ty + (q << 3)][tx] = g_Xf[(long)(r0 + ty + (q << 3)) * 256 + c0 + tx];
    __syncthreads();
#pragma unroll
    for (int q = 0; q < 4; q++) {
        int m = c0 + ty + (q << 3);
        int row = r0 + tx;
        int bs = row >> 7, c = row & 127;
        float2 v = tile[tx][ty + (q << 3)];
        long base = ((long)m * 256 + bs) * 2 * 256;
        __nv_bfloat16 h, l;
        bf_split(v.x, h, l); g_Ab[base + c] = h;        g_Ab[base + 256 + c] = l;
        bf_split(v.y, h, l); g_Ab[base + 128 + c] = h;  g_Ab[base + 384 + c] = l;
    }
}

// ---------------- tensor-core GEMM with compact-W expansion ----------------
template <int NT>
__global__ void __launch_bounds__(256) k_gemm() {
    __shared__ __nv_bfloat16 As[2][128][40];
    __shared__ __nv_bfloat16 Bs[2][128][40];

    int nb = blockIdx.x, mb = blockIdx.y, mo = blockIdx.z;
    int t = threadIdx.x;
    int wid = t >> 5, lane = t & 31;
    int wm = wid & 1, wn = wid >> 1;
    int g = lane >> 2, tq = lane & 3;

    int isImOut = (NT == 768) ? (nb >= 3 ? 1 : 0) : nb;
    int oI      = (NT == 768) ? (nb - (isImOut ? 3 : 0)) : 0;
    const __nv_bfloat16* Wm = (NT == 768)
        ? (g_Wqc + (long)mo * (3L * 2 * 128 * 2 * 128) + (long)oI * (2L * 128 * 2 * 128))
        : (g_Woc + (long)mo * (2L * 128 * 2 * 128));

    float acc[4][4][4];
#pragma unroll
    for (int i = 0; i < 4; i++)
#pragma unroll
        for (int j = 0; j < 4; j++)
#pragma unroll
            for (int r = 0; r < 4; r++) acc[i][j][r] = 0.0f;

    const __nv_bfloat16* Abase = g_Ab + ((long)mo * 256 + mb * 128) * 2 * 256;

    int lr = t & 127, lh = t >> 7;
    for (int k0 = 0; k0 < 256; k0 += 32) {
        {
            const float4* sa = (const float4*)(Abase + ((long)lr * 2 + lh) * 256 + k0);
            float4* da = (float4*)&As[lh][lr][0];
            da[0] = sa[0]; da[1] = sa[1]; da[2] = sa[2]; da[3] = sa[3];

            int isImK = (k0 >= 128) ? 1 : 0;
            int p = isImK ^ isImOut;
            unsigned flip = (isImK && !isImOut) ? 0x80008000u : 0u;
            const uint4* sb = (const uint4*)(Wm + ((long)p * 128 + lr) * 2 * 128 + (long)lh * 128 + (k0 & 127));
            uint4* db = (uint4*)&Bs[lh][lr][0];
#pragma unroll
            for (int q = 0; q < 4; q++) {
                uint4 v = sb[q];
                v.x ^= flip; v.y ^= flip; v.z ^= flip; v.w ^= flip;
                db[q] = v;
            }
        }
        __syncthreads();
#pragma unroll
        for (int ks = 0; ks < 2; ks++) {
            unsigned ah[4][4], al[4][4], bh[4][2], bl[4][2];
            int kb = ks * 16 + 2 * tq;
#pragma unroll
            for (int mt = 0; mt < 4; mt++) {
                int row = wm * 64 + mt * 16 + g;
                ah[mt][0] = *(const unsigned*)&As[0][row][kb];
                ah[mt][1] = *(const unsigned*)&As[0][row + 8][kb];
                ah[mt][2] = *(const unsigned*)&As[0][row][kb + 8];
                ah[mt][3] = *(const unsigned*)&As[0][row + 8][kb + 8];
                al[mt][0] = *(const unsigned*)&As[1][row][kb];
                al[mt][1] = *(const unsigned*)&As[1][row + 8][kb];
                al[mt][2] = *(const unsigned*)&As[1][row][kb + 8];
                al[mt][3] = *(const unsigned*)&As[1][row + 8][kb + 8];
            }
#pragma unroll
            for (int nt = 0; nt < 4; nt++) {
                int col = wn * 32 + nt * 8 + g;
                bh[nt][0] = *(const unsigned*)&Bs[0][col][kb];
                bh[nt][1] = *(const unsigned*)&Bs[0][col][kb + 8];
                bl[nt][0] = *(const unsigned*)&Bs[1][col][kb];
                bl[nt][1] = *(const unsigned*)&Bs[1][col][kb + 8];
            }
#define MMA(d, a, b0, b1)                                                     \
    asm volatile("mma.sync.aligned.m16n8k16.row.col.f32.bf16.bf16.f32 "       \
                 "{%0,%1,%2,%3}, {%4,%5,%6,%7}, {%8,%9}, {%0,%1,%2,%3};"      \
                 : "+f"(d[0]), "+f"(d[1]), "+f"(d[2]), "+f"(d[3])             \
                 : "r"(a[0]), "r"(a[1]), "r"(a[2]), "r"(a[3]), "r"(b0), "r"(b1))
#pragma unroll
            for (int mt = 0; mt < 4; mt++)
#pragma unroll
                for (int nt = 0; nt < 4; nt++) {
                    MMA(acc[mt][nt], ah[mt], bh[nt][0], bh[nt][1]);
                    MMA(acc[mt][nt], ah[mt], bl[nt][0], bl[nt][1]);
                    MMA(acc[mt][nt], al[mt], bh[nt][0], bh[nt][1]);
                }
#undef MMA
        }
        __syncthreads();
    }

    if (NT == 768) {
        // direct epilogue into Fq / Fk / Veff layouts
#pragma unroll
        for (int mt = 0; mt < 4; mt++)
#pragma unroll
            for (int nt = 0; nt < 4; nt++) {
                int c = wn * 32 + nt * 8 + 2 * tq;
#pragma unroll
                for (int rr = 0; rr < 2; rr++) {
                    int bs = mb * 128 + wm * 64 + mt * 16 + g + rr * 8;
                    float2 val = make_float2(acc[mt][nt][rr * 2], acc[mt][nt][rr * 2 + 1]);
                    if (oI == 0)
                        *(float2*)&g_Fq[(long)bs * 65536 + (2L * mo + isImOut) * 128 + c] = val;
                    else if (oI == 1)
                        *(float2*)&g_Fk[(long)bs * 65536 + (2L * mo + isImOut) * 128 + c] = val;
                    else {
                        float* vp = isImOut ? g_VeI : g_VeR;
                        *(float2*)&vp[((long)bs * 256 + mo) * 128 + c] = val;
                    }
                }
            }
    } else {
#pragma unroll
        for (int mt = 0; mt < 4; mt++)
#pragma unroll
            for (int nt = 0; nt < 4; nt++) {
                int row = mb * 128 + wm * 64 + mt * 16 + g;
                long base = ((long)mo * 256 + row) * NT + nb * 128 + wn * 32 + nt * 8 + 2 * tq;
                *(float2*)&g_C2o[base] = make_float2(acc[mt][nt][0], acc[mt][nt][1]);
                *(float2*)&g_C2o[base + 8L * NT] = make_float2(acc[mt][nt][2], acc[mt][nt][3]);
            }
    }
}

// ---------------- scores + bias + softmax ----------------
__global__ void k_scores(const float* __restrict__ amask) {
    int b = blockIdx.x, n = blockIdx.y;
    __shared__ float sq[16 * 132], sk[16 * 132];
    int t = threadIdx.x;
    int i = t >> 4, j = t & 15;
    float D = 0.0f;

    for (int ch = 0; ch < 64; ch++) {
#pragma unroll
        for (int k = 0; k < 8; k++) {
            int e = t + (k << 8);
            int d = e & 15, mcL = (e >> 4) & 7, ii = e >> 7;
            long ga = (long)((b << 4) + ii) * 65536 + (long)((ch << 3) + mcL) * 128 + (n << 4) + d;
            int sa = ii * 132 + (mcL << 4) + d;
            sq[sa] = g_Fq[ga];
            sk[sa] = g_Fk[ga];
        }
        __syncthreads();
        const float4* aq = (const float4*)(sq + i * 132);
        const float4* ak = (const float4*)(sk + j * 132);
#pragma unroll
        for (int r = 0; r < 32; r++) {
            float4 a = aq[r], bb = ak[r];
            D += a.x * bb.x + a.y * bb.y + a.z * bb.z + a.w * bb.w;
        }
        __syncthreads();
    }

    float gsum = 0.0f;
#pragma unroll
    for (int d = 0; d < 16; d++)
        gsum += g_gram[(((b << 7) + (n << 4) + d) << 8) + t];

    float s = (gsum + D * (1.0f / 1024.0f)) * (1.0f / 4096.0f);
    s += amask[(((b & 3) * 8 + n) << 8) + t] + g_cpb[(n << 8) + t];
    float mx = s;
#pragma unroll
    for (int off = 8; off; off >>= 1) mx = fmaxf(mx, __shfl_xor_sync(0xffffffffu, mx, off));
    float e = expf(s - mx);
    float su = e;
#pragma unroll
    for (int off = 8; off; off >>= 1) su += __shfl_xor_sync(0xffffffffu, su, off);
    g_attn[((b * 8 + n) << 8) + t] = e / su;
}

// ---------------- attn x Veff -> realified split A for out GEMM ----------------
__global__ void k_av() {
    int b = blockIdx.x, mch = blockIdx.y;
    __shared__ float2 sV[16][2][128];
    __shared__ float sA[2048];
    int t = threadIdx.x;
#pragma unroll
    for (int k = 0; k < 8; k++) sA[t + (k << 8)] = g_attn[b * 2048 + t + (k << 8)];
#pragma unroll
    for (int k = 0; k < 16; k++) {
        int e = t + (k << 8);
        int c = e & 127, mo = (e >> 7) & 1, j = e >> 8;
        long vi = ((long)((b << 4) + j) * 256 + (mch << 1) + mo) * 128 + c;
        sV[j][mo][c] = make_float2(g_VeR[vi], g_VeI[vi]);
    }
    __syncthreads();
    int c = t & 127, mo = t >> 7;
    int n = c >> 4;
    float2 acc[16];
#pragma unroll
    for (int ii = 0; ii < 16; ii++) acc[ii] = make_float2(0.0f, 0.0f);
#pragma unroll
    for (int jj = 0; jj < 16; jj++) {
        float2 v = sV[jj][mo][c];
#pragma unroll
        for (int ii = 0; ii < 16; ii++) {
            float a = sA[(n << 8) + (ii << 4) + jj];
            acc[ii].x += a * v.x;
            acc[ii].y += a * v.y;
        }
    }
    int m = (mch << 1) + mo;
#pragma unroll
    for (int ii = 0; ii < 16; ii++) {
        int bs = (b << 4) + ii;
        long base = ((long)m * 256 + bs) * 2 * 256;
        __nv_bfloat16 h, l;
        bf_split(acc[ii].x, h, l); g_Ab[base + c] = h;       g_Ab[base + 256 + c] = l;
        bf_split(acc[ii].y, h, l); g_Ab[base + 128 + c] = h; g_Ab[base + 384 + c] = l;
    }
}

// ---------------- transpose C2o [m][j] -> Y2T [j][m] ----------------
__global__ void k_prepS() {
    __shared__ float tile[32][33];
    int c0 = blockIdx.x << 5, r0 = blockIdx.y << 5;
    int tx = threadIdx.x, ty = threadIdx.y;
#pragma unroll
    for (int q = 0; q < 4; q++)
        tile[ty + (q << 3)][tx] = g_C2o[(long)(r0 + ty + (q << 3)) * 65536 + c0 + tx];
    __syncthreads();
#pragma unroll
    for (int q = 0; q < 4; q++)
        g_Y2T[(long)(c0 + ty + (q << 3)) * 256 + r0 + tx] = tile[tx][ty + (q << 3)];
}

// ---------------- inverse low-mode irfft2 with fused un-shift store ----------------
__global__ void k_inv(float* __restrict__ dout) {
    int bs = blockIdx.x, o = blockIdx.y;
    __shared__ float2 Ssm[256];
    __shared__ float2 Gs[32][17];
    __shared__ float2 ytabs[512];
    __shared__ float2 tw[32];
    int t = threadIdx.x;
    if (t < 32) tw[t] = g_tw[t];
    ytabs[t]       = g_ytab[t];
    ytabs[t + 256] = g_ytab[t + 256];
    Ssm[t] = make_float2(g_Y2T[((long)bs * 256 + o) * 256 + t],
                         g_Y2T[((long)bs * 256 + 128 + o) * 256 + t]);
    __syncthreads();
#pragma unroll
    for (int q = 0; q < 2; q++) {
        int idx = t + (q << 8);
        int u = idx >> 4, ky = idx & 15;
        float gr = 0.0f, gi = 0.0f;
        int a = 0;
#pragma unroll
        for (int kx = 0; kx < 16; kx++) {
            float2 s = Ssm[(kx << 4) + ky];
            float2 w = tw[a];
            gr += s.x * w.x - s.y * w.y;
            gi += s.x * w.y + s.y * w.x;
            a = (a + u) & 31;
        }
        Gs[u][ky] = make_float2(gr, gi);
    }
    __syncthreads();

    int b = bs >> 4, s = bs & 15, qx = s >> 2, qy = s & 3;
#pragma unroll
    for (int q = 0; q < 4; q++) {
        int idx = t + (q << 8);
        int u = idx >> 5, v = idx & 31;
        float acc = 0.0f;
#pragma unroll
        for (int ky = 0; ky < 16; ky++) {
            float2 g = Gs[u][ky];
            float2 w = ytabs[(ky << 5) + v];
            acc += g.x * w.x - g.y * w.y;
        }
        float y = acc * (2.0f / 1024.0f);
        int I = ((qx << 5) + u + 16) & 127;
        int J = ((qy << 5) + v + 16) & 127;
        int s2 = ((I >> 5) << 2) | (J >> 5);
        long off = ((long)(b * 16 + s2) * 128) * NP + ((I & 31) << 5) + (J & 31);
        dout[off + (long)o * NP] = y;
    }
}

// ---------------- launch ----------------
extern "C" void kernel_launch(void* const* d_in, const int* in_sizes, int n_in,
                              void* d_out, int out_size) {
    const float* seq    = (const float*)d_in[0];
    const float* qkv_wr = (const float*)d_in[1];
    const float* qkv_wi = (const float*)d_in[2];
    const float* out_wr = (const float*)d_in[3];
    const float* out_wi = (const float*)d_in[4];
    const float* cpb_w1 = (const float*)d_in[5];
    const float* cpb_b1 = (const float*)d_in[6];
    const float* cpb_w2 = (const float*)d_in[7];
    const float* amask  = (const float*)d_in[8];
    float* outp = (float*)d_out;

    k_init<<<1, 512>>>();
    k_cpb<<<1, 256>>>(cpb_w1, cpb_b1, cpb_w2);
    k_wprep<<<dim3(384, 8), 256>>>(qkv_wr, qkv_wi, 0);
    k_wprep<<<dim3(128, 8), 256>>>(out_wr, out_wi, 1);

    k_fwd<<<dim3(256, 128), 256>>>(seq);
    k_gram<<<dim3(16, 128), 256>>>(seq);
    k_gram2<<<dim3(16, 128), 256>>>();
    k_prepA<<<dim3(8, 1024), dim3(32, 8)>>>();

    k_gemm<768><<<dim3(6, 2, 256), 256>>>();   // -> Fq, Fk, Veff directly

    k_scores<<<dim3(16, 8), 256>>>(amask);
    k_av<<<dim3(16, 128), 256>>>();

    k_gemm<256><<<dim3(2, 2, 256), 256>>>();
    k_prepS<<<dim3(2048, 8), dim3(32, 8)>>>();
    k_inv<<<dim3(256, 128), 256>>>(outp);
}